// round 8
// baseline (speedup 1.0000x reference)
#include <cuda_runtime.h>
#include <cuda_fp16.h>
#include <cstdint>

#define BB 4
#define NN 4096
#define FF 128
#define ALPHA 0.1f
#define KC 128

// ---------------- device scratch ----------------
__device__ float g_w1[FF], g_w2[FF], g_c[2];
__device__ __align__(16) float2 g_e1[BB * NN];   // (exp(wh1), exp(0.1*wh1))
__device__ __align__(16) float2 g_e2[BB * NN];   // (exp(wh2), exp(0.1*wh2))
__device__ float g_h[BB * NN * FF];                             // 8 MB
__device__ __align__(16) __half g_vph[BB * NN * FF];            // 4 MB fp16 [b][j][f]
__device__ __align__(16) uint32_t g_adjbits[BB * NN * (NN/32)]; // 8.4 MB bitmask

__device__ __forceinline__ float leaky(float x) { return fmaxf(x, ALPHA * x); }

// ---------------- mma.sync helpers ----------------
__device__ __forceinline__ void mma16816(float* d, const uint32_t* a, const uint32_t* b) {
    asm volatile("mma.sync.aligned.m16n8k16.row.col.f32.f16.f16.f32 "
        "{%0,%1,%2,%3},{%4,%5,%6,%7},{%8,%9},{%0,%1,%2,%3};"
        : "+f"(d[0]), "+f"(d[1]), "+f"(d[2]), "+f"(d[3])
        : "r"(a[0]), "r"(a[1]), "r"(a[2]), "r"(a[3]), "r"(b[0]), "r"(b[1]));
}
__device__ __forceinline__ void ldsm_x4(uint32_t* r, uint32_t addr) {
    asm volatile("ldmatrix.sync.aligned.m8n8.x4.shared.b16 {%0,%1,%2,%3},[%4];"
        : "=r"(r[0]), "=r"(r[1]), "=r"(r[2]), "=r"(r[3]) : "r"(addr));
}
__device__ __forceinline__ void ldsm_x4_t(uint32_t* r, uint32_t addr) {
    asm volatile("ldmatrix.sync.aligned.m8n8.x4.trans.shared.b16 {%0,%1,%2,%3},[%4];"
        : "=r"(r[0]), "=r"(r[1]), "=r"(r[2]), "=r"(r[3]) : "r"(addr));
}
__device__ __forceinline__ uint32_t smem_u32(const void* p) {
    uint32_t a;
    asm("{ .reg .u64 t; cvta.to.shared.u64 t, %1; cvt.u32.u64 %0, t; }" : "=r"(a) : "l"(p));
    return a;
}
__device__ __forceinline__ void cp16(uint32_t dst, const void* src) {
    asm volatile("cp.async.cg.shared.global [%0], [%1], 16;" :: "r"(dst), "l"(src) : "memory");
}
#define CP_COMMIT() asm volatile("cp.async.commit_group;" ::: "memory")
#define CP_WAIT0()  asm volatile("cp.async.wait_group 0;" ::: "memory")
__device__ __forceinline__ uint32_t h2u(__half2 h) { return *(uint32_t*)&h; }

// ---------------- kernel 0: pack adj into bitmask (vectorized) -------------
__global__ void __launch_bounds__(256) k_pack(const int* __restrict__ adj) {
    int t = blockIdx.x * 256 + threadIdx.x;
    const int4* p = (const int4*)adj + (size_t)t * 2;
    int4 a = p[0], b = p[1];
    uint32_t bits =
        (uint32_t)(a.x != 0)        | ((uint32_t)(a.y != 0) << 1) |
        ((uint32_t)(a.z != 0) << 2) | ((uint32_t)(a.w != 0) << 3) |
        ((uint32_t)(b.x != 0) << 4) | ((uint32_t)(b.y != 0) << 5) |
        ((uint32_t)(b.z != 0) << 6) | ((uint32_t)(b.w != 0) << 7);
    int lane = threadIdx.x & 31;
    uint32_t my = bits << ((lane & 3) * 8);
    my |= __shfl_xor_sync(0xffffffffu, my, 1);
    my |= __shfl_xor_sync(0xffffffffu, my, 2);
    if ((lane & 3) == 0) g_adjbits[t >> 2] = my;
}

// ---------------- kernel 1: fold a into Q/K projections ----------------
__global__ void k_prep(const float* __restrict__ Wq_w, const float* __restrict__ Wq_b,
                       const float* __restrict__ Wk_w, const float* __restrict__ Wk_b,
                       const float* __restrict__ a) {
    int f = threadIdx.x;
    float s1 = 0.f, s2 = 0.f;
    for (int o = 0; o < FF; o++) {
        s1 += Wq_w[o * FF + f] * a[o];
        s2 += Wk_w[o * FF + f] * a[FF + o];
    }
    g_w1[f] = s1; g_w2[f] = s2;
    if (f == 0) {
        float c1 = 0.f, c2 = 0.f;
        for (int o = 0; o < FF; o++) { c1 += Wq_b[o] * a[o]; c2 += Wk_b[o] * a[FF + o]; }
        g_c[0] = c1; g_c[1] = c2;
    }
}

// ---------------- kernel 2: Wh -> (exp(wh), exp(0.1 wh)) pairs -------------
__global__ void k_wh(const float* __restrict__ q, const float* __restrict__ k) {
    int warp = threadIdx.x >> 5, lane = threadIdx.x & 31;
    int row = blockIdx.x * 8 + warp;
    const float* src; const float* w; float c; float2* dst; int r;
    if (row < BB * NN) { src = q; w = g_w1; c = g_c[0]; dst = g_e1; r = row; }
    else               { src = k; w = g_w2; c = g_c[1]; dst = g_e2; r = row - BB * NN; }
    float4 x  = ((const float4*)(src + (size_t)r * FF))[lane];
    float4 ww = ((const float4*)w)[lane];
    float s = x.x * ww.x + x.y * ww.y + x.z * ww.z + x.w * ww.w;
    #pragma unroll
    for (int o = 16; o > 0; o >>= 1) s += __shfl_xor_sync(0xffffffffu, s, o);
    if (lane == 0) {
        float wh = s + c;
        dst[r] = make_float2(__expf(wh), __expf(ALPHA * wh));
    }
}

// ---------------- kernel 3/5: 128x128 projection GEMM ----------------
__global__ void __launch_bounds__(256)
k_gemm128(const float* __restrict__ in, const float* __restrict__ W,
          const float* __restrict__ bias, float* __restrict__ outf, int mode) {
    __shared__ __align__(16) float in_s[32][33];
    __shared__ __align__(16) float wt_s[32][132];
    int t = threadIdx.x;
    int i0 = blockIdx.x * 32;
    int w = t >> 5, l = t & 31;
    float acc[4][4] = {};
    for (int kt = 0; kt < FF; kt += 32) {
        __syncthreads();
        {
            int r = t >> 3, f4 = t & 7;
            float4 v = *(const float4*)(in + (size_t)(i0 + r) * FF + kt + f4 * 4);
            in_s[r][f4 * 4 + 0] = v.x; in_s[r][f4 * 4 + 1] = v.y;
            in_s[r][f4 * 4 + 2] = v.z; in_s[r][f4 * 4 + 3] = v.w;
        }
        #pragma unroll
        for (int kk = 0; kk < 4; kk++) {
            int idx = t + kk * 256;
            int o = idx >> 3, f4 = idx & 7;
            float4 v = *(const float4*)(W + (size_t)o * FF + kt + f4 * 4);
            wt_s[f4 * 4 + 0][o] = v.x; wt_s[f4 * 4 + 1][o] = v.y;
            wt_s[f4 * 4 + 2][o] = v.z; wt_s[f4 * 4 + 3][o] = v.w;
        }
        __syncthreads();
        #pragma unroll
        for (int f = 0; f < 32; f++) {
            float4 wv = *(const float4*)&wt_s[f][l * 4];
            #pragma unroll
            for (int r = 0; r < 4; r++) {
                float iv = in_s[w * 4 + r][f];
                acc[r][0] += iv * wv.x; acc[r][1] += iv * wv.y;
                acc[r][2] += iv * wv.z; acc[r][3] += iv * wv.w;
            }
        }
    }
    float4 bv = make_float4(0.f, 0.f, 0.f, 0.f);
    if (mode == 1) bv = *(const float4*)(bias + l * 4);
    #pragma unroll
    for (int r = 0; r < 4; r++) {
        float4 o4;
        o4.x = acc[r][0] + bv.x; o4.y = acc[r][1] + bv.y;
        o4.z = acc[r][2] + bv.z; o4.w = acc[r][3] + bv.w;
        size_t base = (size_t)(i0 + w * 4 + r) * FF + l * 4;
        if (mode == 0) {
            o4.x = leaky(o4.x); o4.y = leaky(o4.y); o4.z = leaky(o4.z); o4.w = leaky(o4.w);
            *(float4*)(outf + base) = o4;
        } else {
            __half2 h01 = __floats2half2_rn(o4.x, o4.y);
            __half2 h23 = __floats2half2_rn(o4.z, o4.w);
            *(uint2*)(g_vph + base) = make_uint2(h2u(h01), h2u(h23));
        }
    }
}

// ---------------- kernel 4: pipelined masked softmax-agg (512 threads) -----
// KC=128: P tiles 128x128 fp16, V tiles 128x128 fp16, double buffered
#define PSTRIDE 272          // 128 halves + 8 pad
#define PBUF 34816           // 128 * 272
#define VSTRIDE 272
#define VBUF 34816
#define PH_BASE 0            // 2 x 34816
#define VH_BASE 69632        // 2 x 34816
#define WH2_OFF 139264       // e2 pairs: 4096 float2 = 32768
#define RS_OFF  172032       // 512 floats
#define IV_OFF  174080       // 128 floats
#define SM_TOTAL 174592

__global__ void __launch_bounds__(512, 1)
k_attn_mma() {
    extern __shared__ char sm[];
    int t = threadIdx.x;
    int lane = t & 31, wid = t >> 5;
    int b = blockIdx.y;
    int it0 = blockIdx.x * 128;

    int mwarp = (wid >> 2) * 32;     // 4 warp-rows x 32 rows
    int nwarp = (wid & 3) * 32;      // 4 warp-cols x 32 cols

    uint32_t sbase = smem_u32(sm);
    uint32_t aoffH = sbase + PH_BASE + (uint32_t)(mwarp + (lane & 15)) * PSTRIDE + (lane >> 4) * 16;
    uint32_t boffH = sbase + VH_BASE + (uint32_t)(lane & 15) * VSTRIDE + (nwarp + (lane >> 4) * 8) * 2;

    // P-gen mapping: 4 threads per row, 32 j's each
    int prow = t >> 2;
    int pq = t & 3;
    float2 e1 = g_e1[b * NN + it0 + prow];
    float ea = e1.x, ea2 = e1.y;
    const uint32_t* maskp = g_adjbits + (size_t)(b * NN + it0 + prow) * (NN / 32) + pq;
    const __half* vph = g_vph + (size_t)b * NN * FF;
    char* pdstH = sm + PH_BASE + prow * PSTRIDE + pq * 64;
    // e2 pairs: pq block of 32 pairs = 16 float4
    const float4* e2q = (const float4*)(sm + WH2_OFF) + pq * 16;

    // V cp.async mapping: 4 threads per row, 4 x 16B each
    int vr = t >> 2, vs = t & 3;
    uint32_t vdst = sbase + VH_BASE + vr * VSTRIDE + vs * 64;
    const __half* vsrc0 = vph + (size_t)vr * FF + vs * 32;

    // stage e2 pairs for this batch (4096 float2 = 2048 float4, 4/thread)
    {
        float4* d = (float4*)(sm + WH2_OFF);
        const float4* s = (const float4*)(g_e2 + b * NN);
        #pragma unroll
        for (int kk = 0; kk < 4; kk++) d[t + kk * 512] = s[t + kk * 512];
    }

    float acc[2][4][4];
    #pragma unroll
    for (int mi = 0; mi < 2; mi++)
        #pragma unroll
        for (int n8 = 0; n8 < 4; n8++)
            #pragma unroll
            for (int x = 0; x < 4; x++) acc[mi][n8][x] = 0.f;
    float rs = 0.f;

    uint2 hiR[8];

    // genP: 32 j's; p = mask ? max(ea*E2, ea2*E2a) : 0
    auto genP = [&](int c, uint32_t mask) {
        #pragma unroll
        for (int qq = 0; qq < 8; qq++) {
            float4 A = e2q[c * 64 + qq * 2];       // (E2 j0, E2a j0, E2 j1, E2a j1)
            float4 Bq = e2q[c * 64 + qq * 2 + 1];  // j2, j3
            float p0 = (mask >> (qq * 4 + 0)) & 1u ? fmaxf(ea * A.x,  ea2 * A.y)  : 0.f;
            float p1 = (mask >> (qq * 4 + 1)) & 1u ? fmaxf(ea * A.z,  ea2 * A.w)  : 0.f;
            float p2 = (mask >> (qq * 4 + 2)) & 1u ? fmaxf(ea * Bq.x, ea2 * Bq.y) : 0.f;
            float p3 = (mask >> (qq * 4 + 3)) & 1u ? fmaxf(ea * Bq.z, ea2 * Bq.w) : 0.f;
            rs += (p0 + p1) + (p2 + p3);
            __half2 h01 = __floats2half2_rn(p0, p1);
            __half2 h23 = __floats2half2_rn(p2, p3);
            hiR[qq] = make_uint2(h2u(h01), h2u(h23));
        }
    };
    auto storeP = [&](int buf) {
        char* dh = pdstH + buf * PBUF;
        #pragma unroll
        for (int qq = 0; qq < 8; qq++)
            *(uint2*)(dh + qq * 8) = hiR[qq];
    };
    auto loadV = [&](int buf, int j0) {
        const __half* s = vsrc0 + (size_t)j0 * FF;
        uint32_t d = vdst + buf * VBUF;
        #pragma unroll
        for (int kk = 0; kk < 4; kk++)
            cp16(d + kk * 16, s + kk * 8);
        CP_COMMIT();
    };

    // masks: word index = c*4 + pq (stride 4 words per 128-j chunk)
    uint32_t mA = __ldg(maskp);
    uint32_t mB = __ldg(maskp + 4);
    loadV(0, 0);
    __syncthreads();                      // e2 staged
    genP(0, mA);
    storeP(0);
    CP_WAIT0();
    __syncthreads();

    for (int c = 0; c < NN / KC; c++) {
        int buf = c & 1, nbuf = buf ^ 1;
        bool has_next = (c + 1) < (NN / KC);
        uint32_t mC = 0;
        if (c + 2 < NN / KC) mC = __ldg(maskp + (size_t)(c + 2) * 4);
        if (has_next) {
            loadV(nbuf, (c + 1) * KC);
            genP(c + 1, mB);
        }
        // ---- MMA on buffer `buf`: 8 k16 steps ----
        uint32_t pb = aoffH + buf * PBUF;
        uint32_t vb = boffH + buf * VBUF;
        #pragma unroll
        for (int kk = 0; kk < 8; kk++) {
            uint32_t ah[2][4];
            ldsm_x4(ah[0], pb + kk * 32);
            ldsm_x4(ah[1], pb + 16 * PSTRIDE + kk * 32);
            #pragma unroll
            for (int nb = 0; nb < 2; nb++) {
                uint32_t bh[4];
                ldsm_x4_t(bh, vb + kk * 16 * VSTRIDE + nb * 32);
                #pragma unroll
                for (int mi = 0; mi < 2; mi++) {
                    mma16816(acc[mi][nb * 2 + 0], ah[mi], bh + 0);
                    mma16816(acc[mi][nb * 2 + 1], ah[mi], bh + 2);
                }
            }
        }
        if (has_next) storeP(nbuf);
        mB = mC;
        CP_WAIT0();
        __syncthreads();
    }

    // ---- normalizers: 4 partial sums per row ----
    ((float*)(sm + RS_OFF))[t] = rs;
    __syncthreads();
    if (t < 128) {
        const float* rss = (const float*)(sm + RS_OFF) + t * 4;
        ((float*)(sm + IV_OFF))[t] = 1.0f / ((rss[0] + rss[1]) + (rss[2] + rss[3]));
    }
    __syncthreads();
    const float* inv = (const float*)(sm + IV_OFF);

    // ---- write h ----
    #pragma unroll
    for (int mi = 0; mi < 2; mi++) {
        int r0 = mwarp + mi * 16 + (lane >> 2);
        float iv0 = inv[r0], iv1 = inv[r0 + 8];
        #pragma unroll
        for (int n8 = 0; n8 < 4; n8++) {
            int col = nwarp + n8 * 8 + (lane & 3) * 2;
            float2 v0 = make_float2(acc[mi][n8][0] * iv0, acc[mi][n8][1] * iv0);
            float2 v1 = make_float2(acc[mi][n8][2] * iv1, acc[mi][n8][3] * iv1);
            *(float2*)(g_h + (size_t)(b * NN + it0 + r0) * FF + col) = v0;
            *(float2*)(g_h + (size_t)(b * NN + it0 + r0 + 8) * FF + col) = v1;
        }
    }
}

// ---------------- launch ----------------
extern "C" void kernel_launch(void* const* d_in, const int* in_sizes, int n_in,
                              void* d_out, int out_size) {
    const float* q    = (const float*)d_in[0];
    const float* k    = (const float*)d_in[1];
    const float* v    = (const float*)d_in[2];
    const int*   adj  = (const int*)  d_in[3];
    const float* Wq_w = (const float*)d_in[4];
    const float* Wq_b = (const float*)d_in[5];
    const float* Wk_w = (const float*)d_in[6];
    const float* Wk_b = (const float*)d_in[7];
    const float* Wv_w = (const float*)d_in[8];
    const float* Wv_b = (const float*)d_in[9];
    const float* a    = (const float*)d_in[10];
    const float* Wo_w = (const float*)d_in[11];
    float* out = (float*)d_out;

    void* h_ptr = nullptr;
    cudaGetSymbolAddress(&h_ptr, g_h);

    cudaFuncSetAttribute(k_attn_mma, cudaFuncAttributeMaxDynamicSharedMemorySize, SM_TOTAL);

    k_pack<<<(BB * NN * NN) / (256 * 8), 256>>>(adj);
    k_prep<<<1, 128>>>(Wq_w, Wq_b, Wk_w, Wk_b, a);
    k_wh<<<(2 * BB * NN) / 8, 256>>>(q, k);
    k_gemm128<<<BB * NN / 32, 256>>>(v, Wv_w, Wv_b, nullptr, 1);
    {
        dim3 grid(NN / 128, BB);
        k_attn_mma<<<grid, 512, SM_TOTAL>>>();
    }
    k_gemm128<<<BB * NN / 32, 256>>>((const float*)h_ptr, Wo_w, nullptr, out, 0);
}